// round 4
// baseline (speedup 1.0000x reference)
#include <cuda_runtime.h>
#include <math.h>

#define NPT 8192
#define L2E 1.4426950408889634f
#define LN2 0.6931471805599453f
#define K0  (-13.0f)                 // log2(1/8192), exact

#define TILE 512
#define RPW 8
#define NPAIR 4
#define THREADS 128
#define ROWS_CTA 32                   // 4 warps * 8 rows
#define CTA_PER_PROB 256              // NPT / ROWS_CTA

typedef unsigned long long u64;

// Persistent scratch (no allocation allowed anywhere)
__device__ float4 d_ptsX[NPT], d_ptsY[NPT];   // (x,y,z, |p|^2/2)
__device__ float  d_du[2][4][NPT];            // [parity][f,g,pp,qq][i]
__device__ float  d_ls[2][4][NPT];            // row lse (log2 units) per phase

__device__ __forceinline__ float ex2(float x) {
    float y; asm("ex2.approx.f32 %0, %1;" : "=f"(y) : "f"(x)); return y;
}
__device__ __forceinline__ u64 pk2(float lo, float hi) {
    u64 d;
    asm("mov.b64 %0, {%1, %2};" : "=l"(d)
        : "r"(__float_as_uint(lo)), "r"(__float_as_uint(hi)));
    return d;
}
__device__ __forceinline__ void up2(u64 v, float& lo, float& hi) {
    unsigned a, b;
    asm("mov.b64 {%0, %1}, %2;" : "=r"(a), "=r"(b) : "l"(v));
    lo = __uint_as_float(a); hi = __uint_as_float(b);
}
__device__ __forceinline__ u64 ffma2(u64 a, u64 b, u64 c) {
    u64 d; asm("fma.rn.f32x2 %0, %1, %2, %3;" : "=l"(d) : "l"(a), "l"(b), "l"(c));
    return d;
}
__device__ __forceinline__ u64 fadd2(u64 a, u64 b) {
    u64 d; asm("add.rn.f32x2 %0, %1, %2;" : "=l"(d) : "l"(a), "l"(b));
    return d;
}

__global__ void init_kernel(const float* __restrict__ X, const float* __restrict__ Y) {
    int i = blockIdx.x * blockDim.x + threadIdx.x;
    if (i >= NPT) return;
    float x0 = X[3*i], x1 = X[3*i+1], x2 = X[3*i+2];
    d_ptsX[i] = make_float4(x0, x1, x2, 0.5f * (x0*x0 + x1*x1 + x2*x2));
    float y0 = Y[3*i], y1 = Y[3*i+1], y2 = Y[3*i+2];
    d_ptsY[i] = make_float4(y0, y1, y2, 0.5f * (y0*y0 + y1*y1 + y2*y2));
#pragma unroll
    for (int p = 0; p < 4; p++) {
        d_du[0][p][i] = 0.f;
        // safe lse upper bound at eps0=4: t <= K0 + sc*1.5, sc = L2E/4
        d_ls[0][p][i] = K0 + 0.6f;
    }
}

// One launch = one Sinkhorn phase; one-pass softmin, packed f32x2, predicted M.
// prob 0: f  <- reduce over Y with dual g   (rows = X)
// prob 1: g  <- reduce over X with dual f   (rows = Y)
// prob 2: pp <- reduce over X with dual pp  (rows = X)
// prob 3: qq <- reduce over Y with dual qq  (rows = Y)
__global__ void __launch_bounds__(THREADS)
phase_kernel(float eps, float ratio_inv, int avg, int par) {
    __shared__ u64 scx[TILE], scy[TILE], scz[TILE], scw[TILE];

    int prob = blockIdx.x >> 8;            // / CTA_PER_PROB
    int rb   = blockIdx.x & (CTA_PER_PROB - 1);

    const float4* __restrict__ cpts = (prob == 1 || prob == 2) ? d_ptsX : d_ptsY;
    const float4* __restrict__ rpts = (prob == 0 || prob == 2) ? d_ptsX : d_ptsY;
    int didx = (prob == 0) ? 1 : (prob == 1) ? 0 : prob;
    const float* __restrict__ cdual  = d_du[par][didx];
    const float* __restrict__ oldpot = d_du[par][prob];
    const float* __restrict__ oldlse = d_ls[par][prob];
    float* __restrict__ outpot       = d_du[par ^ 1][prob];
    float* __restrict__ outlse       = d_ls[par ^ 1][prob];

    int warp = threadIdx.x >> 5;
    int lane = threadIdx.x & 31;
    int row0 = rb * ROWS_CTA + warp * RPW;

    float sc = L2E / eps;                  // logits in log2 units

    float Mv[RPW], S[RPW];
    u64 A0[NPAIR], A1[NPAIR], A2[NPAIR], NM[NPAIR];
#pragma unroll
    for (int rp = 0; rp < NPAIR; rp++) {
        float4 pa = rpts[row0 + 2*rp];
        float4 pb = rpts[row0 + 2*rp + 1];
        A0[rp] = pk2(pa.x * sc, pb.x * sc);
        A1[rp] = pk2(pa.y * sc, pb.y * sc);
        A2[rp] = pk2(pa.z * sc, pb.z * sc);
        // predicted safe max: (lse_prev - K0) scales by eps_prev/eps; +4 slack
        float ma = fmaf(oldlse[row0 + 2*rp]     - K0, ratio_inv, K0 + 4.0f);
        float mb = fmaf(oldlse[row0 + 2*rp + 1] - K0, ratio_inv, K0 + 4.0f);
        Mv[2*rp] = ma; Mv[2*rp + 1] = mb;
        NM[rp] = pk2(-ma, -mb);
        S[2*rp] = 0.f; S[2*rp + 1] = 0.f;
    }

    for (int tb = 0; tb < NPT; tb += TILE) {
        __syncthreads();
        for (int j = threadIdx.x; j < TILE; j += THREADS) {
            float4 p = cpts[tb + j];
            float cb = fmaf(sc, cdual[tb + j] - p.w, K0);   // column bias
            scx[j] = pk2(p.x, p.x);
            scy[j] = pk2(p.y, p.y);
            scz[j] = pk2(p.z, p.z);
            scw[j] = pk2(cb,  cb);
        }
        __syncthreads();
#pragma unroll 4
        for (int k = 0; k < TILE / 32; k++) {
            int j = k * 32 + lane;
            u64 cx = scx[j], cy = scy[j], cz = scz[j], cw = scw[j];
#pragma unroll
            for (int rp = 0; rp < NPAIR; rp++) {
                u64 v = fadd2(cw, NM[rp]);          // {cb-M0, cb-M1}
                v = ffma2(A2[rp], cz, v);
                v = ffma2(A1[rp], cy, v);
                v = ffma2(A0[rp], cx, v);
                float lo, hi; up2(v, lo, hi);
                S[2*rp]     += ex2(lo);
                S[2*rp + 1] += ex2(hi);
            }
        }
    }

    // warp reduce sums (M is warp-uniform per row, so S adds directly)
#pragma unroll
    for (int r = 0; r < RPW; r++)
#pragma unroll
        for (int o = 16; o; o >>= 1)
            S[r] += __shfl_xor_sync(0xffffffffu, S[r], o);

    // lse + safety: S in (1e-25, 1e25) guarantees no overflow / denormal loss
    float lse[RPW];
    int bad = 0;
#pragma unroll
    for (int r = 0; r < RPW; r++) {
        if (!(S[r] > 1e-25f && S[r] < 1e25f)) bad = 1;
        lse[r] = Mv[r] + log2f(S[r]);
    }

    if (__any_sync(0xffffffffu, bad)) {
        // cold exact fallback: warp-local, gmem-direct, online softmax (no syncs)
#pragma unroll 1
        for (int r = 0; r < RPW; r++) {
            float4 q = rpts[row0 + r];
            float b0 = q.x * sc, b1 = q.y * sc, b2 = q.z * sc;
            float mm = -3.0e38f, ss = 0.f;
            for (int j = lane; j < NPT; j += 32) {
                float4 p = cpts[j];
                float t = fmaf(b0, p.x, fmaf(b1, p.y,
                          fmaf(b2, p.z, fmaf(sc, cdual[j] - p.w, K0))));
                float mn = fmaxf(mm, t);
                ss = fmaf(ss, ex2(mm - mn), ex2(t - mn));
                mm = mn;
            }
            for (int o = 16; o; o >>= 1) {
                float mo = __shfl_xor_sync(0xffffffffu, mm, o);
                float so = __shfl_xor_sync(0xffffffffu, ss, o);
                float mn = fmaxf(mm, mo);
                ss = ss * ex2(mm - mn) + so * ex2(mo - mn);
                mm = mn;
            }
            lse[r] = mm + log2f(ss);
        }
    }

    if (lane == 0) {
#pragma unroll
        for (int r = 0; r < RPW; r++) {
            int row = row0 + r;
            float res = rpts[row].w - eps * LN2 * lse[r];
            outpot[row] = avg ? 0.5f * (oldpot[row] + res) : res;
            outlse[row] = lse[r];
        }
    }
}

__global__ void reduce_kernel(float* out, int out_size) {
    __shared__ double sh[256];
    double s = 0.0;
    for (int i = threadIdx.x; i < NPT; i += 256)
        s += (double)(d_du[1][0][i] - d_du[1][2][i])
           + (double)(d_du[1][1][i] - d_du[1][3][i]);
    sh[threadIdx.x] = s;
    __syncthreads();
    for (int o = 128; o > 0; o >>= 1) {
        if (threadIdx.x < o) sh[threadIdx.x] += sh[threadIdx.x + o];
        __syncthreads();
    }
    if (threadIdx.x == 0) {
        float v = (float)(sh[0] / (double)NPT);
        for (int k = 0; k < out_size; k++) out[k] = v;
    }
}

extern "C" void kernel_launch(void* const* d_in, const int* in_sizes, int n_in,
                              void* d_out, int out_size) {
    const float* X = (const float*)d_in[0];   // source_points [8192,3]
    const float* Y = (const float*)d_in[1];   // target_points [8192,3]

    // geomloss eps schedule (double, matches reference)
    double sched[96];
    int ns = 0;
    double e      = pow(2.0, 2.0);
    double target = pow(0.01, 2.0);
    double ratio  = pow(0.9, 2.0);
    while (e > target) { sched[ns++] = e; e *= ratio; }

    init_kernel<<<NPT / 256, 256>>>(X, Y);

    // phase 0: init (zero duals, avg=0, eps=sched[0])
    // phases 1..ns: scan over full schedule (avg=1)
    // phase ns+1: final extrapolation at eps_final (avg=0)
    double eps_prev = sched[0];
    for (int p = 0; p <= ns + 1; p++) {
        double eps; int avg;
        if (p == 0)       { eps = sched[0];     avg = 0; }
        else if (p <= ns) { eps = sched[p - 1]; avg = 1; }
        else              { eps = target;       avg = 0; }
        float ratio_inv = (float)(eps_prev / eps);
        phase_kernel<<<4 * CTA_PER_PROB, THREADS>>>((float)eps, ratio_inv, avg, p & 1);
        eps_prev = eps;
    }
    // 53 phases total; last write parity = 1
    reduce_kernel<<<1, 256>>>((float*)d_out, out_size);
}